// round 1
// baseline (speedup 1.0000x reference)
#include <cuda_runtime.h>
#include <cuda_bf16.h>
#include <cstdint>

// Problem constants
#define BATCH  8
#define SEQ    1024
#define DIM    1024
#define HEADS  16
#define HDIM   64
#define TOKENS (BATCH * SEQ)          // 8192
#define QKVDIM (3 * DIM)              // 3072
#define SCALE  0.03125f               // 1024^-0.5

// Scratch (device globals: allocation-guard safe)
__device__ float g_qkv[(size_t)TOKENS * QKVDIM];   // [8192, 3072]
__device__ float g_attn[(size_t)TOKENS * DIM];     // [8192, 1024]

// ----------------------------------------------------------------------------
// Tiled fp32 SGEMM: C[M,N] = A[M,K] @ B[K,N] (+ bias[N] if bias != nullptr)
// Block 64x64, BK=32, 256 threads, 4x4 per thread. M,N,K multiples of 64/32.
// ----------------------------------------------------------------------------
__global__ __launch_bounds__(256) void sgemm64(
    const float* __restrict__ A, const float* __restrict__ B,
    const float* __restrict__ bias, float* __restrict__ C,
    int M, int N, int K)
{
    __shared__ float As[32][65];   // [k][m], padded: bank = (k+m)%32
    __shared__ float Bs[32][64];   // [k][n]

    const int tx = threadIdx.x & 15;          // 0..15 -> 4 cols each
    const int ty = threadIdx.x >> 4;          // 0..15 -> 4 rows each
    const int row0 = blockIdx.y * 64;
    const int col0 = blockIdx.x * 64;

    float acc[4][4] = {};

    for (int k0 = 0; k0 < K; k0 += 32) {
        // Load A tile 64x32 (coalesced on K), store transposed As[k][m]
        #pragma unroll
        for (int i = threadIdx.x; i < 64 * 32; i += 256) {
            int r = i >> 5, c = i & 31;
            As[c][r] = A[(size_t)(row0 + r) * K + (k0 + c)];
        }
        // Load B tile 32x64 (coalesced on N)
        #pragma unroll
        for (int i = threadIdx.x; i < 32 * 64; i += 256) {
            int r = i >> 6, c = i & 63;
            Bs[r][c] = B[(size_t)(k0 + r) * N + (col0 + c)];
        }
        __syncthreads();

        #pragma unroll
        for (int kk = 0; kk < 32; kk++) {
            float a[4];
            #pragma unroll
            for (int i = 0; i < 4; i++) a[i] = As[kk][ty * 4 + i];
            float4 bv = *(const float4*)&Bs[kk][tx * 4];
            float b[4] = {bv.x, bv.y, bv.z, bv.w};
            #pragma unroll
            for (int i = 0; i < 4; i++)
                #pragma unroll
                for (int j = 0; j < 4; j++)
                    acc[i][j] += a[i] * b[j];
        }
        __syncthreads();
    }

    float4 bb = make_float4(0.f, 0.f, 0.f, 0.f);
    if (bias) bb = *(const float4*)&bias[col0 + tx * 4];

    #pragma unroll
    for (int i = 0; i < 4; i++) {
        int r = row0 + ty * 4 + i;
        float4 v = make_float4(acc[i][0] + bb.x, acc[i][1] + bb.y,
                               acc[i][2] + bb.z, acc[i][3] + bb.w);
        *(float4*)&C[(size_t)r * N + col0 + tx * 4] = v;
    }
}

// ----------------------------------------------------------------------------
// Flash-attention (fp32, online softmax).
// grid: (SEQ/64, HEADS, BATCH); block: 256 threads = 8 warps.
// Each block: 64 query rows x all 1024 keys of one (batch, head).
// Warp w owns rows w*8..w*8+7. Lane split: lane_r = lane>>4 (row half),
// lane_k = lane&15 (key/dim quarter group).
// ----------------------------------------------------------------------------
#define ATTN_SMEM_FLOATS (64 * 65 + 64 * 65 + 64 * 64 + 8 * 8 * 64)  // 16512
#define ATTN_SMEM_BYTES  (ATTN_SMEM_FLOATS * 4)                      // 66048

__global__ __launch_bounds__(256) void attn64(
    const float* __restrict__ qkv, float* __restrict__ out)
{
    extern __shared__ float sm[];
    float* Qs = sm;                 // [64][65]
    float* Ks = Qs + 64 * 65;       // [64][65]
    float* Vs = Ks + 64 * 65;       // [64][64]
    float* Ps = Vs + 64 * 64;       // [8 warps][8 rows][64 keys]

    const int tid   = threadIdx.x;
    const int warp  = tid >> 5;
    const int lane  = tid & 31;
    const int lane_r = lane >> 4;   // 0..1
    const int lane_k = lane & 15;   // 0..15

    const int qt    = blockIdx.x;
    const int head  = blockIdx.y;
    const int batch = blockIdx.z;

    const size_t base = (size_t)batch * SEQ * QKVDIM + (size_t)head * HDIM;

    // Load Q tile [64][64]
    for (int i = tid; i < 64 * 64; i += 256) {
        int r = i >> 6, c = i & 63;
        Qs[r * 65 + c] = qkv[base + (size_t)(qt * 64 + r) * QKVDIM + c];
    }

    const int rloc = warp * 8 + lane_r * 4;   // first of 4 rows this lane owns
    float m_i[4], l_i[4], o[4][4];
    #pragma unroll
    for (int i = 0; i < 4; i++) {
        m_i[i] = -1e30f; l_i[i] = 0.f;
        #pragma unroll
        for (int j = 0; j < 4; j++) o[i][j] = 0.f;
    }

    __syncthreads();

    for (int jt = 0; jt < SEQ / 64; jt++) {
        // Load K, V tiles [64][64]
        for (int i = tid; i < 64 * 64; i += 256) {
            int r = i >> 6, c = i & 63;
            size_t g = base + (size_t)(jt * 64 + r) * QKVDIM + c;
            Ks[r * 65 + c] = qkv[g + DIM];       // K block
            Vs[r * 64 + c] = qkv[g + 2 * DIM];   // V block
        }
        __syncthreads();

        // S = Q Kᵀ (per-lane 4x4 micro-tile: rows rloc..+3, keys lane_k*4..+3)
        float s[4][4] = {};
        #pragma unroll 16
        for (int k = 0; k < 64; k++) {
            float a[4], b[4];
            #pragma unroll
            for (int i = 0; i < 4; i++) a[i] = Qs[(rloc + i) * 65 + k];
            #pragma unroll
            for (int j = 0; j < 4; j++) b[j] = Ks[(lane_k * 4 + j) * 65 + k];
            #pragma unroll
            for (int i = 0; i < 4; i++)
                #pragma unroll
                for (int j = 0; j < 4; j++)
                    s[i][j] += a[i] * b[j];
        }

        // Online softmax per row (reduce across the 16-lane key group)
        #pragma unroll
        for (int i = 0; i < 4; i++) {
            float tm = -1e30f;
            #pragma unroll
            for (int j = 0; j < 4; j++) { s[i][j] *= SCALE; tm = fmaxf(tm, s[i][j]); }
            #pragma unroll
            for (int off = 1; off < 16; off <<= 1)
                tm = fmaxf(tm, __shfl_xor_sync(0xffffffffu, tm, off));

            float mn = fmaxf(m_i[i], tm);
            float alpha = __expf(m_i[i] - mn);
            m_i[i] = mn;

            float rs = 0.f;
            #pragma unroll
            for (int j = 0; j < 4; j++) { s[i][j] = __expf(s[i][j] - mn); rs += s[i][j]; }
            #pragma unroll
            for (int off = 1; off < 16; off <<= 1)
                rs += __shfl_xor_sync(0xffffffffu, rs, off);

            l_i[i] = l_i[i] * alpha + rs;
            #pragma unroll
            for (int j = 0; j < 4; j++) {
                o[i][j] *= alpha;
                Ps[warp * 512 + (lane_r * 4 + i) * 64 + lane_k * 4 + j] = s[i][j];
            }
        }
        __syncwarp();   // P is per-warp: make stores visible within warp

        // O += P @ V   (lane owns rows rloc..+3, dims lane_k*4..+3)
        #pragma unroll 8
        for (int jk = 0; jk < 64; jk++) {
            float4 v = *(const float4*)&Vs[jk * 64 + lane_k * 4];
            #pragma unroll
            for (int i = 0; i < 4; i++) {
                float p = Ps[warp * 512 + (lane_r * 4 + i) * 64 + jk];
                o[i][0] += p * v.x;
                o[i][1] += p * v.y;
                o[i][2] += p * v.z;
                o[i][3] += p * v.w;
            }
        }
        __syncthreads();   // protect Ks/Vs (and Ps) before next tile overwrite
    }

    // Epilogue: out[token][head*64 + d] = o / l
    #pragma unroll
    for (int i = 0; i < 4; i++) {
        float inv = 1.f / l_i[i];
        int token = batch * SEQ + qt * 64 + rloc + i;
        float4 v = make_float4(o[i][0] * inv, o[i][1] * inv,
                               o[i][2] * inv, o[i][3] * inv);
        *(float4*)&out[(size_t)token * DIM + head * HDIM + lane_k * 4] = v;
    }
}

// ----------------------------------------------------------------------------
// Launch
// ----------------------------------------------------------------------------
extern "C" void kernel_launch(void* const* d_in, const int* in_sizes, int n_in,
                              void* d_out, int out_size)
{
    const float* x     = (const float*)d_in[0];   // [8,1024,1024]
    const float* w_qkv = (const float*)d_in[1];   // [1024,3072]
    const float* w_out = (const float*)d_in[2];   // [1024,1024]
    const float* b_out = (const float*)d_in[3];   // [1024]
    float* out = (float*)d_out;

    void* p_qkv = nullptr;
    void* p_attn = nullptr;
    cudaGetSymbolAddress(&p_qkv, g_qkv);
    cudaGetSymbolAddress(&p_attn, g_attn);
    float* qkv  = (float*)p_qkv;
    float* attn = (float*)p_attn;

    cudaFuncSetAttribute(attn64, cudaFuncAttributeMaxDynamicSharedMemorySize,
                         ATTN_SMEM_BYTES);

    // 1) qkv = x @ w_qkv          [8192,3072]
    sgemm64<<<dim3(QKVDIM / 64, TOKENS / 64), 256>>>(
        x, w_qkv, nullptr, qkv, TOKENS, QKVDIM, DIM);

    // 2) attention                 [8192,1024]
    attn64<<<dim3(SEQ / 64, HEADS, BATCH), 256, ATTN_SMEM_BYTES>>>(qkv, attn);

    // 3) out = attn @ w_out + b    [8192,1024]
    sgemm64<<<dim3(DIM / 64, TOKENS / 64), 256>>>(
        attn, w_out, b_out, out, TOKENS, DIM, DIM);
}

// round 3
// speedup vs baseline: 1.8781x; 1.8781x over previous
#include <cuda_runtime.h>
#include <cuda_bf16.h>
#include <cstdint>

// Problem constants
#define BATCH  8
#define SEQ    1024
#define DIM    1024
#define HEADS  16
#define HDIM   64
#define TOKENS (BATCH * SEQ)          // 8192
#define QKVDIM (3 * DIM)              // 3072
#define SCALE  0.03125f               // 1024^-0.5

// ---------------------------------------------------------------------------
// Scratch (device globals: allocation-guard safe)
// ---------------------------------------------------------------------------
__device__ float g_qkv[(size_t)TOKENS * QKVDIM];
__device__ float g_attn[(size_t)TOKENS * DIM];
__device__ __nv_bfloat16 g_xhi[(size_t)TOKENS * DIM];
__device__ __nv_bfloat16 g_xlo[(size_t)TOKENS * DIM];
__device__ __nv_bfloat16 g_w1hi[(size_t)QKVDIM * DIM];      // w_qkv^T [3072][1024]
__device__ __nv_bfloat16 g_w1lo[(size_t)QKVDIM * DIM];
__device__ __nv_bfloat16 g_w2hi[(size_t)DIM * DIM];         // w_out^T [1024][1024]
__device__ __nv_bfloat16 g_w2lo[(size_t)DIM * DIM];
__device__ __nv_bfloat16 g_ahi[(size_t)TOKENS * DIM];
__device__ __nv_bfloat16 g_alo[(size_t)TOKENS * DIM];

// ---------------------------------------------------------------------------
// Helpers
// ---------------------------------------------------------------------------
__device__ __forceinline__ uint32_t smem_u32(const void* p) {
    uint32_t a;
    asm("{ .reg .u64 t; cvta.to.shared.u64 t, %1; cvt.u32.u64 %0, t; }" : "=r"(a) : "l"(p));
    return a;
}

__device__ __forceinline__ void cp_async16(uint32_t dst, const void* src) {
    asm volatile("cp.async.cg.shared.global [%0], [%1], 16;\n" :: "r"(dst), "l"(src));
}
#define CP_COMMIT() asm volatile("cp.async.commit_group;\n" ::: "memory")
#define CP_WAIT1()  asm volatile("cp.async.wait_group 1;\n" ::: "memory")
#define CP_WAIT0()  asm volatile("cp.async.wait_group 0;\n" ::: "memory")

__device__ __forceinline__ void ldsm_x4(uint32_t* r, uint32_t addr) {
    asm volatile("ldmatrix.sync.aligned.m8n8.x4.shared.b16 {%0,%1,%2,%3}, [%4];"
                 : "=r"(r[0]), "=r"(r[1]), "=r"(r[2]), "=r"(r[3]) : "r"(addr));
}

__device__ __forceinline__ void mma_bf16(float* d, const uint32_t* a, const uint32_t* b) {
    asm volatile("mma.sync.aligned.m16n8k16.row.col.f32.bf16.bf16.f32 "
                 "{%0,%1,%2,%3}, {%4,%5,%6,%7}, {%8,%9}, {%0,%1,%2,%3};"
                 : "+f"(d[0]), "+f"(d[1]), "+f"(d[2]), "+f"(d[3])
                 : "r"(a[0]), "r"(a[1]), "r"(a[2]), "r"(a[3]), "r"(b[0]), "r"(b[1]));
}

// ---------------------------------------------------------------------------
// Split-bf16 HMMA GEMM: C[M,N] = (Ahi+Alo)[M,K] @ (Whi+Wlo)[N,K]^T (+bias)
// Block 128x128, BK=32, 256 threads (8 warps, 2x4 grid of 64x32 warp tiles),
// double-buffered cp.async, XOR-swizzled smem -> conflict-free ldmatrix.
// ---------------------------------------------------------------------------
#define GK     1024
#define BK     32
#define NITER  (GK / BK)               // 32
#define TILEB  (128 * 64)              // bytes: [128 rows][32 bf16 = 64B]
#define STAGEB (4 * TILEB)             // 32 KB (Ahi, Alo, Whi, Wlo)
#define GEMM_SMEM (2 * STAGEB)         // 64 KB

__global__ __launch_bounds__(256, 1) void gemm_mma(
    const __nv_bfloat16* __restrict__ Ahi, const __nv_bfloat16* __restrict__ Alo,
    const __nv_bfloat16* __restrict__ Whi, const __nv_bfloat16* __restrict__ Wlo,
    const float* __restrict__ bias, float* __restrict__ C, int N)
{
    extern __shared__ char sm[];
    const uint32_t sbase = smem_u32(sm);
    const int tid  = threadIdx.x;
    const int lane = tid & 31;
    const int warp = tid >> 5;
    const int wm = warp & 1;              // 2 warp rows (m)
    const int wn = warp >> 1;             // 4 warp cols (n)
    const int m0 = blockIdx.y * 128;
    const int n0 = blockIdx.x * 128;

    float acc[4][4][4];
    #pragma unroll
    for (int i = 0; i < 4; i++)
        #pragma unroll
        for (int j = 0; j < 4; j++)
            #pragma unroll
            for (int q = 0; q < 4; q++) acc[i][j][q] = 0.f;

    const __nv_bfloat16* gs[4] = {Ahi, Alo, Whi, Wlo};
    const int r0s[4] = {m0, m0, n0, n0};

    auto soff = [&](int s, int t) -> uint32_t { return sbase + s * STAGEB + t * TILEB; };

    auto load_stage = [&](int s, int k0) {
        #pragma unroll
        for (int t = 0; t < 4; t++) {
            const char* gp = (const char*)(gs[t] + (size_t)r0s[t] * GK + k0);
            #pragma unroll
            for (int j = 0; j < 2; j++) {
                int id = tid + j * 256;           // 0..511 chunk ids
                int r = id >> 2, c = id & 3;      // row 0..127, 16B chunk 0..3
                uint32_t sw = r * 64 + ((c ^ ((r >> 1) & 3)) << 4);
                cp_async16(soff(s, t) + sw, gp + (size_t)r * (GK * 2) + c * 16);
            }
        }
        CP_COMMIT();
    };

    load_stage(0, 0);
    load_stage(1, BK);

    // ldmatrix lane addressing
    const int sub = lane >> 3, rin = lane & 7;
    const int a_row_off = (sub & 1) * 8 + rin;   // mats: m0-7/k0-7, m8-15/k0-7, m0-7/k8-15, m8-15/k8-15
    const int a_chunk   = sub >> 1;
    const int b_row_off = (sub >> 1) * 8 + rin;  // mats: n0-7/k0-7, n0-7/k8-15, n8-15/k0-7, n8-15/k8-15
    const int b_chunk   = sub & 1;

    for (int it = 0; it < NITER; it++) {
        const int s = it & 1;
        if (it == NITER - 1) { CP_WAIT0(); } else { CP_WAIT1(); }
        __syncthreads();

        const uint32_t aH = soff(s, 0), aL = soff(s, 1);
        const uint32_t wH = soff(s, 2), wL = soff(s, 3);

        #pragma unroll
        for (int ks = 0; ks < 2; ks++) {          // two k16 steps per BK=32
            uint32_t Ah[4][4], Al[4][4], Bh[4][2], Bl[4][2];

            #pragma unroll
            for (int mi = 0; mi < 4; mi++) {
                int row = wm * 64 + mi * 16 + a_row_off;
                int c = ks * 2 + a_chunk;
                uint32_t off = row * 64 + ((c ^ ((row >> 1) & 3)) << 4);
                ldsm_x4(Ah[mi], aH + off);
                ldsm_x4(Al[mi], aL + off);
            }
            #pragma unroll
            for (int p = 0; p < 2; p++) {
                int row = wn * 32 + p * 16 + b_row_off;
                int c = ks * 2 + b_chunk;
                uint32_t off = row * 64 + ((c ^ ((row >> 1) & 3)) << 4);
                uint32_t t0[4], t1[4];
                ldsm_x4(t0, wH + off);
                ldsm_x4(t1, wL + off);
                Bh[p*2  ][0] = t0[0]; Bh[p*2  ][1] = t0[1];
                Bh[p*2+1][0] = t0[2]; Bh[p*2+1][1] = t0[3];
                Bl[p*2  ][0] = t1[0]; Bl[p*2  ][1] = t1[1];
                Bl[p*2+1][0] = t1[2]; Bl[p*2+1][1] = t1[3];
            }

            #pragma unroll
            for (int mi = 0; mi < 4; mi++)
                #pragma unroll
                for (int ni = 0; ni < 4; ni++) {
                    mma_bf16(acc[mi][ni], Ah[mi], Bh[ni]);   // hi*hi
                    mma_bf16(acc[mi][ni], Ah[mi], Bl[ni]);   // hi*lo
                    mma_bf16(acc[mi][ni], Al[mi], Bh[ni]);   // lo*hi
                }
        }
        __syncthreads();
        if (it + 2 < NITER) load_stage(s, (it + 2) * BK);
    }

    // Epilogue: m16n8 accumulator layout -> fp32 C (+bias)
    const int g = lane >> 2, c2 = (lane & 3) * 2;
    #pragma unroll
    for (int mi = 0; mi < 4; mi++) {
        int row = m0 + wm * 64 + mi * 16 + g;
        #pragma unroll
        for (int ni = 0; ni < 4; ni++) {
            int col = n0 + wn * 32 + ni * 8 + c2;
            float b0 = 0.f, b1 = 0.f;
            if (bias) { b0 = bias[col]; b1 = bias[col + 1]; }
            float2 v0 = make_float2(acc[mi][ni][0] + b0, acc[mi][ni][1] + b1);
            float2 v1 = make_float2(acc[mi][ni][2] + b0, acc[mi][ni][3] + b1);
            *(float2*)&C[(size_t)row * N + col] = v0;
            *(float2*)&C[(size_t)(row + 8) * N + col] = v1;
        }
    }
}

// ---------------------------------------------------------------------------
// fp32 -> bf16 hi/lo split (elementwise, float4)
// ---------------------------------------------------------------------------
__global__ __launch_bounds__(256) void split_kernel(
    const float* __restrict__ in, __nv_bfloat16* __restrict__ hi,
    __nv_bfloat16* __restrict__ lo, int n4)
{
    int i = blockIdx.x * blockDim.x + threadIdx.x;
    if (i >= n4) return;
    float4 v = ((const float4*)in)[i];
    __nv_bfloat16 h[4], l[4];
    float f[4] = {v.x, v.y, v.z, v.w};
    #pragma unroll
    for (int j = 0; j < 4; j++) {
        h[j] = __float2bfloat16(f[j]);
        l[j] = __float2bfloat16(f[j] - __bfloat162float(h[j]));
    }
    ((ushort4*)hi)[i] = make_ushort4(__bfloat16_as_ushort(h[0]), __bfloat16_as_ushort(h[1]),
                                     __bfloat16_as_ushort(h[2]), __bfloat16_as_ushort(h[3]));
    ((ushort4*)lo)[i] = make_ushort4(__bfloat16_as_ushort(l[0]), __bfloat16_as_ushort(l[1]),
                                     __bfloat16_as_ushort(l[2]), __bfloat16_as_ushort(l[3]));
}

// ---------------------------------------------------------------------------
// fp32 [K][N] -> transposed bf16 hi/lo [N][K]
// ---------------------------------------------------------------------------
__global__ __launch_bounds__(256) void splitT_kernel(
    const float* __restrict__ w, __nv_bfloat16* __restrict__ thi,
    __nv_bfloat16* __restrict__ tlo, int K, int N)
{
    __shared__ float t[32][33];
    const int n0 = blockIdx.x * 32, k0 = blockIdx.y * 32;
    const int tx = threadIdx.x & 31, ty = threadIdx.x >> 5;
    #pragma unroll
    for (int j = ty; j < 32; j += 8)
        t[j][tx] = w[(size_t)(k0 + j) * N + n0 + tx];
    __syncthreads();
    #pragma unroll
    for (int j = ty; j < 32; j += 8) {
        float v = t[tx][j];
        __nv_bfloat16 h = __float2bfloat16(v);
        __nv_bfloat16 l = __float2bfloat16(v - __bfloat162float(h));
        thi[(size_t)(n0 + j) * K + k0 + tx] = h;
        tlo[(size_t)(n0 + j) * K + k0 + tx] = l;
    }
}

// ----------------------------------------------------------------------------
// Flash-attention (fp32, online softmax) — unchanged (known-good)
// ----------------------------------------------------------------------------
#define ATTN_SMEM_FLOATS (64 * 65 + 64 * 65 + 64 * 64 + 8 * 8 * 64)
#define ATTN_SMEM_BYTES  (ATTN_SMEM_FLOATS * 4)

__global__ __launch_bounds__(256) void attn64(
    const float* __restrict__ qkv, float* __restrict__ out)
{
    extern __shared__ float smf[];
    float* Qs = smf;
    float* Ks = Qs + 64 * 65;
    float* Vs = Ks + 64 * 65;
    float* Ps = Vs + 64 * 64;

    const int tid   = threadIdx.x;
    const int warp  = tid >> 5;
    const int lane  = tid & 31;
    const int lane_r = lane >> 4;
    const int lane_k = lane & 15;

    const int qt    = blockIdx.x;
    const int head  = blockIdx.y;
    const int batch = blockIdx.z;

    const size_t base = (size_t)batch * SEQ * QKVDIM + (size_t)head * HDIM;

    for (int i = tid; i < 64 * 64; i += 256) {
        int r = i >> 6, c = i & 63;
        Qs[r * 65 + c] = qkv[base + (size_t)(qt * 64 + r) * QKVDIM + c];
    }

    const int rloc = warp * 8 + lane_r * 4;
    float m_i[4], l_i[4], o[4][4];
    #pragma unroll
    for (int i = 0; i < 4; i++) {
        m_i[i] = -1e30f; l_i[i] = 0.f;
        #pragma unroll
        for (int j = 0; j < 4; j++) o[i][j] = 0.f;
    }

    __syncthreads();

    for (int jt = 0; jt < SEQ / 64; jt++) {
        for (int i = tid; i < 64 * 64; i += 256) {
            int r = i >> 6, c = i & 63;
            size_t gofs = base + (size_t)(jt * 64 + r) * QKVDIM + c;
            Ks[r * 65 + c] = qkv[gofs + DIM];
            Vs[r * 64 + c] = qkv[gofs + 2 * DIM];
        }
        __syncthreads();

        float s[4][4] = {};
        #pragma unroll 16
        for (int k = 0; k < 64; k++) {
            float a[4], b[4];
            #pragma unroll
            for (int i = 0; i < 4; i++) a[i] = Qs[(rloc + i) * 65 + k];
            #pragma unroll
            for (int j = 0; j < 4; j++) b[j] = Ks[(lane_k * 4 + j) * 65 + k];
            #pragma unroll
            for (int i = 0; i < 4; i++)
                #pragma unroll
                for (int j = 0; j < 4; j++)
                    s[i][j] += a[i] * b[j];
        }

        #pragma unroll
        for (int i = 0; i < 4; i++) {
            float tm = -1e30f;
            #pragma unroll
            for (int j = 0; j < 4; j++) { s[i][j] *= SCALE; tm = fmaxf(tm, s[i][j]); }
            #pragma unroll
            for (int off = 1; off < 16; off <<= 1)
                tm = fmaxf(tm, __shfl_xor_sync(0xffffffffu, tm, off));

            float mn = fmaxf(m_i[i], tm);
            float alpha = __expf(m_i[i] - mn);
            m_i[i] = mn;

            float rs = 0.f;
            #pragma unroll
            for (int j = 0; j < 4; j++) { s[i][j] = __expf(s[i][j] - mn); rs += s[i][j]; }
            #pragma unroll
            for (int off = 1; off < 16; off <<= 1)
                rs += __shfl_xor_sync(0xffffffffu, rs, off);

            l_i[i] = l_i[i] * alpha + rs;
            #pragma unroll
            for (int j = 0; j < 4; j++) {
                o[i][j] *= alpha;
                Ps[warp * 512 + (lane_r * 4 + i) * 64 + lane_k * 4 + j] = s[i][j];
            }
        }
        __syncwarp();

        #pragma unroll 8
        for (int jk = 0; jk < 64; jk++) {
            float4 v = *(const float4*)&Vs[jk * 64 + lane_k * 4];
            #pragma unroll
            for (int i = 0; i < 4; i++) {
                float p = Ps[warp * 512 + (lane_r * 4 + i) * 64 + jk];
                o[i][0] += p * v.x;
                o[i][1] += p * v.y;
                o[i][2] += p * v.z;
                o[i][3] += p * v.w;
            }
        }
        __syncthreads();
    }

    #pragma unroll
    for (int i = 0; i < 4; i++) {
        float inv = 1.f / l_i[i];
        int token = batch * SEQ + qt * 64 + rloc + i;
        float4 v = make_float4(o[i][0] * inv, o[i][1] * inv,
                               o[i][2] * inv, o[i][3] * inv);
        *(float4*)&out[(size_t)token * DIM + head * HDIM + lane_k * 4] = v;
    }
}

// ----------------------------------------------------------------------------
// Launch
// ----------------------------------------------------------------------------
extern "C" void kernel_launch(void* const* d_in, const int* in_sizes, int n_in,
                              void* d_out, int out_size)
{
    const float* x     = (const float*)d_in[0];
    const float* w_qkv = (const float*)d_in[1];
    const float* w_out = (const float*)d_in[2];
    const float* b_out = (const float*)d_in[3];
    float* out = (float*)d_out;

    void *p_qkv, *p_attn, *p_xhi, *p_xlo, *p_w1hi, *p_w1lo, *p_w2hi, *p_w2lo, *p_ahi, *p_alo;
    cudaGetSymbolAddress(&p_qkv, g_qkv);
    cudaGetSymbolAddress(&p_attn, g_attn);
    cudaGetSymbolAddress(&p_xhi, g_xhi);
    cudaGetSymbolAddress(&p_xlo, g_xlo);
    cudaGetSymbolAddress(&p_w1hi, g_w1hi);
    cudaGetSymbolAddress(&p_w1lo, g_w1lo);
    cudaGetSymbolAddress(&p_w2hi, g_w2hi);
    cudaGetSymbolAddress(&p_w2lo, g_w2lo);
    cudaGetSymbolAddress(&p_ahi, g_ahi);
    cudaGetSymbolAddress(&p_alo, g_alo);

    float* qkv  = (float*)p_qkv;
    float* attn = (float*)p_attn;

    cudaFuncSetAttribute(attn64, cudaFuncAttributeMaxDynamicSharedMemorySize,
                         ATTN_SMEM_BYTES);
    cudaFuncSetAttribute(gemm_mma, cudaFuncAttributeMaxDynamicSharedMemorySize,
                         GEMM_SMEM);

    // 0) split inputs / weights into bf16 hi+lo
    split_kernel<<<(TOKENS * DIM / 4 + 255) / 256, 256>>>(
        x, (__nv_bfloat16*)p_xhi, (__nv_bfloat16*)p_xlo, TOKENS * DIM / 4);
    splitT_kernel<<<dim3(QKVDIM / 32, DIM / 32), 256>>>(
        w_qkv, (__nv_bfloat16*)p_w1hi, (__nv_bfloat16*)p_w1lo, DIM, QKVDIM);
    splitT_kernel<<<dim3(DIM / 32, DIM / 32), 256>>>(
        w_out, (__nv_bfloat16*)p_w2hi, (__nv_bfloat16*)p_w2lo, DIM, DIM);

    // 1) qkv = x @ w_qkv  (split-bf16 HMMA)         [8192, 3072]
    gemm_mma<<<dim3(QKVDIM / 128, TOKENS / 128), 256, GEMM_SMEM>>>(
        (const __nv_bfloat16*)p_xhi, (const __nv_bfloat16*)p_xlo,
        (const __nv_bfloat16*)p_w1hi, (const __nv_bfloat16*)p_w1lo,
        nullptr, qkv, QKVDIM);

    // 2) attention                                   [8192, 1024]
    attn64<<<dim3(SEQ / 64, HEADS, BATCH), 256, ATTN_SMEM_BYTES>>>(qkv, attn);

    // 3) split attn, out = attn @ w_out + b          [8192, 1024]
    split_kernel<<<(TOKENS * DIM / 4 + 255) / 256, 256>>>(
        attn, (__nv_bfloat16*)p_ahi, (__nv_bfloat16*)p_alo, TOKENS * DIM / 4);
    gemm_mma<<<dim3(DIM / 128, TOKENS / 128), 256, GEMM_SMEM>>>(
        (const __nv_bfloat16*)p_ahi, (const __nv_bfloat16*)p_alo,
        (const __nv_bfloat16*)p_w2hi, (const __nv_bfloat16*)p_w2lo,
        b_out, out, DIM);
}

// round 4
// speedup vs baseline: 3.3333x; 1.7748x over previous
#include <cuda_runtime.h>
#include <cuda_bf16.h>
#include <cstdint>

// Problem constants
#define BATCH  8
#define SEQ    1024
#define DIM    1024
#define HEADS  16
#define HDIM   64
#define TOKENS (BATCH * SEQ)          // 8192
#define QKVDIM (3 * DIM)              // 3072
#define SCALE  0.03125f               // 1024^-0.5

// ---------------------------------------------------------------------------
// Scratch (device globals: allocation-guard safe)
// ---------------------------------------------------------------------------
__device__ __nv_bfloat16 g_xhi[(size_t)TOKENS * DIM];
__device__ __nv_bfloat16 g_xlo[(size_t)TOKENS * DIM];
__device__ __nv_bfloat16 g_w1hi[(size_t)QKVDIM * DIM];      // w_qkv^T [3072][1024]
__device__ __nv_bfloat16 g_w1lo[(size_t)QKVDIM * DIM];
__device__ __nv_bfloat16 g_w2hi[(size_t)DIM * DIM];         // w_out^T [1024][1024]
__device__ __nv_bfloat16 g_w2lo[(size_t)DIM * DIM];
__device__ __nv_bfloat16 g_qkvhi[(size_t)TOKENS * QKVDIM];  // qkv hi [8192][3072]
__device__ __nv_bfloat16 g_qkvlo[(size_t)TOKENS * QKVDIM];
__device__ __nv_bfloat16 g_ahi[(size_t)TOKENS * DIM];
__device__ __nv_bfloat16 g_alo[(size_t)TOKENS * DIM];

// ---------------------------------------------------------------------------
// Helpers
// ---------------------------------------------------------------------------
__device__ __forceinline__ uint32_t smem_u32(const void* p) {
    uint32_t a;
    asm("{ .reg .u64 t; cvta.to.shared.u64 t, %1; cvt.u32.u64 %0, t; }" : "=r"(a) : "l"(p));
    return a;
}

__device__ __forceinline__ void cp_async16(uint32_t dst, const void* src) {
    asm volatile("cp.async.cg.shared.global [%0], [%1], 16;\n" :: "r"(dst), "l"(src));
}
#define CP_COMMIT() asm volatile("cp.async.commit_group;\n" ::: "memory")
#define CP_WAIT2()  asm volatile("cp.async.wait_group 2;\n" ::: "memory")
#define CP_WAIT1()  asm volatile("cp.async.wait_group 1;\n" ::: "memory")
#define CP_WAIT0()  asm volatile("cp.async.wait_group 0;\n" ::: "memory")

__device__ __forceinline__ void ldsm_x4(uint32_t* r, uint32_t addr) {
    asm volatile("ldmatrix.sync.aligned.m8n8.x4.shared.b16 {%0,%1,%2,%3}, [%4];"
                 : "=r"(r[0]), "=r"(r[1]), "=r"(r[2]), "=r"(r[3]) : "r"(addr));
}

__device__ __forceinline__ void ldsm_x4_t(uint32_t* r, uint32_t addr) {
    asm volatile("ldmatrix.sync.aligned.m8n8.x4.trans.shared.b16 {%0,%1,%2,%3}, [%4];"
                 : "=r"(r[0]), "=r"(r[1]), "=r"(r[2]), "=r"(r[3]) : "r"(addr));
}

__device__ __forceinline__ void mma_bf16(float* d, const uint32_t* a, const uint32_t* b) {
    asm volatile("mma.sync.aligned.m16n8k16.row.col.f32.bf16.bf16.f32 "
                 "{%0,%1,%2,%3}, {%4,%5,%6,%7}, {%8,%9}, {%0,%1,%2,%3};"
                 : "+f"(d[0]), "+f"(d[1]), "+f"(d[2]), "+f"(d[3])
                 : "r"(a[0]), "r"(a[1]), "r"(a[2]), "r"(a[3]), "r"(b[0]), "r"(b[1]));
}

// pack two fp32 into bf16x2 (lo -> low half)
__device__ __forceinline__ uint32_t pack_bf16(float lo, float hi) {
    uint32_t d;
    asm("cvt.rn.bf16x2.f32 %0, %1, %2;" : "=r"(d) : "f"(hi), "f"(lo));
    return d;
}
// residual pair after bf16 truncation of (lo, hi) packed in hp
__device__ __forceinline__ uint32_t resid_bf16(uint32_t hp, float lo, float hi) {
    float h0 = __bfloat162float(__ushort_as_bfloat16((unsigned short)(hp & 0xffffu)));
    float h1 = __bfloat162float(__ushort_as_bfloat16((unsigned short)(hp >> 16)));
    return pack_bf16(lo - h0, hi - h1);
}

// ---------------------------------------------------------------------------
// Split-bf16 HMMA GEMM: C = (Ahi+Alo)[M,K] @ (Whi+Wlo)[N,K]^T
// OUT==0: write fp32 C (+bias).  OUT==1: write bf16 hi/lo pair (Chi, Clo).
// Block 128x128, BK=32, 256 threads, double-buffered cp.async, swizzled smem.
// ---------------------------------------------------------------------------
#define GK     1024
#define BK     32
#define NITER  (GK / BK)               // 32
#define TILEB  (128 * 64)              // [128 rows][32 bf16 = 64B]
#define STAGEB (4 * TILEB)             // 32 KB
#define GEMM_SMEM (2 * STAGEB)         // 64 KB

template<int OUT>
__global__ __launch_bounds__(256, 1) void gemm_mma(
    const __nv_bfloat16* __restrict__ Ahi, const __nv_bfloat16* __restrict__ Alo,
    const __nv_bfloat16* __restrict__ Whi, const __nv_bfloat16* __restrict__ Wlo,
    const float* __restrict__ bias, float* __restrict__ C,
    __nv_bfloat16* __restrict__ Chi, __nv_bfloat16* __restrict__ Clo, int N)
{
    extern __shared__ char sm[];
    const uint32_t sbase = smem_u32(sm);
    const int tid  = threadIdx.x;
    const int lane = tid & 31;
    const int warp = tid >> 5;
    const int wm = warp & 1;
    const int wn = warp >> 1;
    const int m0 = blockIdx.y * 128;
    const int n0 = blockIdx.x * 128;

    float acc[4][4][4];
    #pragma unroll
    for (int i = 0; i < 4; i++)
        #pragma unroll
        for (int j = 0; j < 4; j++)
            #pragma unroll
            for (int q = 0; q < 4; q++) acc[i][j][q] = 0.f;

    const __nv_bfloat16* gs[4] = {Ahi, Alo, Whi, Wlo};
    const int r0s[4] = {m0, m0, n0, n0};

    auto soff = [&](int s, int t) -> uint32_t { return sbase + s * STAGEB + t * TILEB; };

    auto load_stage = [&](int s, int k0) {
        #pragma unroll
        for (int t = 0; t < 4; t++) {
            const char* gp = (const char*)(gs[t] + (size_t)r0s[t] * GK + k0);
            #pragma unroll
            for (int j = 0; j < 2; j++) {
                int id = tid + j * 256;
                int r = id >> 2, c = id & 3;
                uint32_t sw = r * 64 + ((c ^ ((r >> 1) & 3)) << 4);
                cp_async16(soff(s, t) + sw, gp + (size_t)r * (GK * 2) + c * 16);
            }
        }
        CP_COMMIT();
    };

    load_stage(0, 0);
    load_stage(1, BK);

    const int sub = lane >> 3, rin = lane & 7;
    const int a_row_off = (sub & 1) * 8 + rin;
    const int a_chunk   = sub >> 1;
    const int b_row_off = (sub >> 1) * 8 + rin;
    const int b_chunk   = sub & 1;

    for (int it = 0; it < NITER; it++) {
        const int s = it & 1;
        if (it == NITER - 1) { CP_WAIT0(); } else { CP_WAIT1(); }
        __syncthreads();

        const uint32_t aH = soff(s, 0), aL = soff(s, 1);
        const uint32_t wH = soff(s, 2), wL = soff(s, 3);

        #pragma unroll
        for (int ks = 0; ks < 2; ks++) {
            uint32_t Ah[4][4], Al[4][4], Bh[4][2], Bl[4][2];

            #pragma unroll
            for (int mi = 0; mi < 4; mi++) {
                int row = wm * 64 + mi * 16 + a_row_off;
                int c = ks * 2 + a_chunk;
                uint32_t off = row * 64 + ((c ^ ((row >> 1) & 3)) << 4);
                ldsm_x4(Ah[mi], aH + off);
                ldsm_x4(Al[mi], aL + off);
            }
            #pragma unroll
            for (int p = 0; p < 2; p++) {
                int row = wn * 32 + p * 16 + b_row_off;
                int c = ks * 2 + b_chunk;
                uint32_t off = row * 64 + ((c ^ ((row >> 1) & 3)) << 4);
                uint32_t t0[4], t1[4];
                ldsm_x4(t0, wH + off);
                ldsm_x4(t1, wL + off);
                Bh[p*2  ][0] = t0[0]; Bh[p*2  ][1] = t0[1];
                Bh[p*2+1][0] = t0[2]; Bh[p*2+1][1] = t0[3];
                Bl[p*2  ][0] = t1[0]; Bl[p*2  ][1] = t1[1];
                Bl[p*2+1][0] = t1[2]; Bl[p*2+1][1] = t1[3];
            }

            #pragma unroll
            for (int mi = 0; mi < 4; mi++)
                #pragma unroll
                for (int ni = 0; ni < 4; ni++) {
                    mma_bf16(acc[mi][ni], Ah[mi], Bh[ni]);
                    mma_bf16(acc[mi][ni], Ah[mi], Bl[ni]);
                    mma_bf16(acc[mi][ni], Al[mi], Bh[ni]);
                }
        }
        __syncthreads();
        if (it + 2 < NITER) load_stage(s, (it + 2) * BK);
    }

    const int g = lane >> 2, c2 = (lane & 3) * 2;
    #pragma unroll
    for (int mi = 0; mi < 4; mi++) {
        int row = m0 + wm * 64 + mi * 16 + g;
        #pragma unroll
        for (int ni = 0; ni < 4; ni++) {
            int col = n0 + wn * 32 + ni * 8 + c2;
            if (OUT == 0) {
                float b0 = 0.f, b1 = 0.f;
                if (bias) { b0 = bias[col]; b1 = bias[col + 1]; }
                float2 v0 = make_float2(acc[mi][ni][0] + b0, acc[mi][ni][1] + b1);
                float2 v1 = make_float2(acc[mi][ni][2] + b0, acc[mi][ni][3] + b1);
                *(float2*)&C[(size_t)row * N + col] = v0;
                *(float2*)&C[(size_t)(row + 8) * N + col] = v1;
            } else {
                uint32_t hp0 = pack_bf16(acc[mi][ni][0], acc[mi][ni][1]);
                uint32_t hp1 = pack_bf16(acc[mi][ni][2], acc[mi][ni][3]);
                uint32_t lp0 = resid_bf16(hp0, acc[mi][ni][0], acc[mi][ni][1]);
                uint32_t lp1 = resid_bf16(hp1, acc[mi][ni][2], acc[mi][ni][3]);
                *(uint32_t*)&Chi[(size_t)row * N + col] = hp0;
                *(uint32_t*)&Chi[(size_t)(row + 8) * N + col] = hp1;
                *(uint32_t*)&Clo[(size_t)row * N + col] = lp0;
                *(uint32_t*)&Clo[(size_t)(row + 8) * N + col] = lp1;
            }
        }
    }
}

// ---------------------------------------------------------------------------
// fp32 -> bf16 hi/lo split (elementwise, float4)
// ---------------------------------------------------------------------------
__global__ __launch_bounds__(256) void split_kernel(
    const float* __restrict__ in, __nv_bfloat16* __restrict__ hi,
    __nv_bfloat16* __restrict__ lo, int n4)
{
    int i = blockIdx.x * blockDim.x + threadIdx.x;
    if (i >= n4) return;
    float4 v = ((const float4*)in)[i];
    __nv_bfloat16 h[4], l[4];
    float f[4] = {v.x, v.y, v.z, v.w};
    #pragma unroll
    for (int j = 0; j < 4; j++) {
        h[j] = __float2bfloat16(f[j]);
        l[j] = __float2bfloat16(f[j] - __bfloat162float(h[j]));
    }
    ((ushort4*)hi)[i] = make_ushort4(__bfloat16_as_ushort(h[0]), __bfloat16_as_ushort(h[1]),
                                     __bfloat16_as_ushort(h[2]), __bfloat16_as_ushort(h[3]));
    ((ushort4*)lo)[i] = make_ushort4(__bfloat16_as_ushort(l[0]), __bfloat16_as_ushort(l[1]),
                                     __bfloat16_as_ushort(l[2]), __bfloat16_as_ushort(l[3]));
}

// ---------------------------------------------------------------------------
// fp32 [K][N] -> transposed bf16 hi/lo [N][K]
// ---------------------------------------------------------------------------
__global__ __launch_bounds__(256) void splitT_kernel(
    const float* __restrict__ w, __nv_bfloat16* __restrict__ thi,
    __nv_bfloat16* __restrict__ tlo, int K, int N)
{
    __shared__ float t[32][33];
    const int n0 = blockIdx.x * 32, k0 = blockIdx.y * 32;
    const int tx = threadIdx.x & 31, ty = threadIdx.x >> 5;
    #pragma unroll
    for (int j = ty; j < 32; j += 8)
        t[j][tx] = w[(size_t)(k0 + j) * N + n0 + tx];
    __syncthreads();
    #pragma unroll
    for (int j = ty; j < 32; j += 8) {
        float v = t[tx][j];
        __nv_bfloat16 h = __float2bfloat16(v);
        __nv_bfloat16 l = __float2bfloat16(v - __bfloat162float(h));
        thi[(size_t)(n0 + j) * K + k0 + tx] = h;
        tlo[(size_t)(n0 + j) * K + k0 + tx] = l;
    }
}

// ---------------------------------------------------------------------------
// HMMA flash attention, split-bf16.
// grid (SEQ/128, HEADS, BATCH); 256 threads = 8 warps; warp w owns q-rows
// 16w..16w+15 of a 128-row q tile. KV tiles of 64 keys, double-buffered.
// S = QhKh+QhKl+QlKh; fp32 online softmax; O += PhVh+PhVl+PlVh.
// smem: Qh/Ql [128][64] + 2 stages of (Kh,Kl,Vh,Vl)[64][64], all bf16,
// rows = 128B, chunk-XOR swizzle.
// ---------------------------------------------------------------------------
#define AT_Q    0
#define AT_QL   16384
#define AT_ST   32768
#define AT_STB  32768
#define AT_KH   0
#define AT_KL   8192
#define AT_VH   16384
#define AT_VL   24576
#define AT_SMEM (AT_ST + 2 * AT_STB)   // 98304

__global__ __launch_bounds__(256, 1) void attn_mma(
    const __nv_bfloat16* __restrict__ qh, const __nv_bfloat16* __restrict__ ql,
    __nv_bfloat16* __restrict__ ohi, __nv_bfloat16* __restrict__ olo)
{
    extern __shared__ char sm[];
    const uint32_t sb = smem_u32(sm);
    const int tid  = threadIdx.x;
    const int lane = tid & 31;
    const int warp = tid >> 5;
    const int sub = lane >> 3, rin = lane & 7;
    const int g = lane >> 2, t = lane & 3;

    const int qt = blockIdx.x, head = blockIdx.y, batch = blockIdx.z;
    const size_t tok0 = (size_t)batch * SEQ;
    const size_t qbase = (tok0 + qt * 128) * QKVDIM + head * HDIM;

    // --- Q tile load (hi+lo), 128 rows x 8 chunks each ---
    #pragma unroll
    for (int j = 0; j < 4; j++) {
        int id = tid + j * 256;
        int r = id >> 3, c = id & 7;
        uint32_t sw = r * 128 + ((c ^ (r & 7)) << 4);
        size_t go = (size_t)r * QKVDIM * 2 + c * 16;
        cp_async16(sb + AT_Q  + sw, (const char*)(qh + qbase) + go);
        cp_async16(sb + AT_QL + sw, (const char*)(ql + qbase) + go);
    }
    CP_COMMIT();

    auto load_kv = [&](int s, int jt) {
        size_t kb = (tok0 + jt * 64) * QKVDIM + DIM + head * HDIM;
        size_t vb = kb + DIM;
        uint32_t st = sb + AT_ST + s * AT_STB;
        #pragma unroll
        for (int j = 0; j < 2; j++) {
            int id = tid + j * 256;
            int r = id >> 3, c = id & 7;
            uint32_t sw = r * 128 + ((c ^ (r & 7)) << 4);
            size_t go = (size_t)r * QKVDIM * 2 + c * 16;
            cp_async16(st + AT_KH + sw, (const char*)(qh + kb) + go);
            cp_async16(st + AT_KL + sw, (const char*)(ql + kb) + go);
            cp_async16(st + AT_VH + sw, (const char*)(qh + vb) + go);
            cp_async16(st + AT_VL + sw, (const char*)(ql + vb) + go);
        }
        CP_COMMIT();
    };

    load_kv(0, 0);
    load_kv(1, 1);

    // --- Q fragments into registers ---
    CP_WAIT2();
    __syncthreads();
    uint32_t Qh[4][4], Ql[4][4];
    {
        int row = warp * 16 + (sub & 1) * 8 + rin;
        #pragma unroll
        for (int s4 = 0; s4 < 4; s4++) {
            int ch = 2 * s4 + (sub >> 1);
            uint32_t off = row * 128 + ((ch ^ (row & 7)) << 4);
            ldsm_x4(Qh[s4], sb + AT_Q  + off);
            ldsm_x4(Ql[s4], sb + AT_QL + off);
        }
    }

    float m0 = -1e30f, m1 = -1e30f, l0 = 0.f, l1 = 0.f;
    float O[8][4];
    #pragma unroll
    for (int b = 0; b < 8; b++)
        #pragma unroll
        for (int q = 0; q < 4; q++) O[b][q] = 0.f;

    for (int jt = 0; jt < SEQ / 64; jt++) {
        const int s = jt & 1;
        if (jt == SEQ / 64 - 1) { CP_WAIT0(); } else { CP_WAIT1(); }
        __syncthreads();
        const uint32_t stb = sb + AT_ST + s * AT_STB;

        // ---- S = Q K^T (3-pass split) ----
        float S[8][4];
        #pragma unroll
        for (int b = 0; b < 8; b++)
            #pragma unroll
            for (int q = 0; q < 4; q++) S[b][q] = 0.f;

        #pragma unroll
        for (int s4 = 0; s4 < 4; s4++) {
            int bch = 2 * s4 + (sub & 1);
            #pragma unroll
            for (int jp = 0; jp < 4; jp++) {
                int row = jp * 16 + (sub >> 1) * 8 + rin;
                uint32_t off = row * 128 + ((bch ^ (row & 7)) << 4);
                uint32_t kh[4], kl[4];
                ldsm_x4(kh, stb + AT_KH + off);
                ldsm_x4(kl, stb + AT_KL + off);
                mma_bf16(S[2*jp],   Qh[s4], kh);
                mma_bf16(S[2*jp],   Qh[s4], kl);
                mma_bf16(S[2*jp],   Ql[s4], kh);
                mma_bf16(S[2*jp+1], Qh[s4], kh + 2);
                mma_bf16(S[2*jp+1], Qh[s4], kl + 2);
                mma_bf16(S[2*jp+1], Ql[s4], kh + 2);
            }
        }

        // ---- online softmax (rows g and g+8 of warp band) ----
        float mx0 = -1e30f, mx1 = -1e30f;
        #pragma unroll
        for (int b = 0; b < 8; b++) {
            #pragma unroll
            for (int q = 0; q < 4; q++) S[b][q] *= SCALE;
            mx0 = fmaxf(mx0, fmaxf(S[b][0], S[b][1]));
            mx1 = fmaxf(mx1, fmaxf(S[b][2], S[b][3]));
        }
        #pragma unroll
        for (int off = 1; off < 4; off <<= 1) {
            mx0 = fmaxf(mx0, __shfl_xor_sync(0xffffffffu, mx0, off));
            mx1 = fmaxf(mx1, __shfl_xor_sync(0xffffffffu, mx1, off));
        }
        float mn0 = fmaxf(m0, mx0), mn1 = fmaxf(m1, mx1);
        float al0 = __expf(m0 - mn0), al1 = __expf(m1 - mn1);
        m0 = mn0; m1 = mn1;

        float rs0 = 0.f, rs1 = 0.f;
        #pragma unroll
        for (int b = 0; b < 8; b++) {
            S[b][0] = __expf(S[b][0] - mn0); rs0 += S[b][0];
            S[b][1] = __expf(S[b][1] - mn0); rs0 += S[b][1];
            S[b][2] = __expf(S[b][2] - mn1); rs1 += S[b][2];
            S[b][3] = __expf(S[b][3] - mn1); rs1 += S[b][3];
        }
        #pragma unroll
        for (int off = 1; off < 4; off <<= 1) {
            rs0 += __shfl_xor_sync(0xffffffffu, rs0, off);
            rs1 += __shfl_xor_sync(0xffffffffu, rs1, off);
        }
        l0 = l0 * al0 + rs0;
        l1 = l1 * al1 + rs1;
        #pragma unroll
        for (int b = 0; b < 8; b++) {
            O[b][0] *= al0; O[b][1] *= al0;
            O[b][2] *= al1; O[b][3] *= al1;
        }

        // ---- O += P V (3-pass split; P frags from S accumulators) ----
        #pragma unroll
        for (int a = 0; a < 4; a++) {
            uint32_t Ph[4], Pl[4];
            Ph[0] = pack_bf16(S[2*a][0],   S[2*a][1]);
            Ph[1] = pack_bf16(S[2*a][2],   S[2*a][3]);
            Ph[2] = pack_bf16(S[2*a+1][0], S[2*a+1][1]);
            Ph[3] = pack_bf16(S[2*a+1][2], S[2*a+1][3]);
            Pl[0] = resid_bf16(Ph[0], S[2*a][0],   S[2*a][1]);
            Pl[1] = resid_bf16(Ph[1], S[2*a][2],   S[2*a][3]);
            Pl[2] = resid_bf16(Ph[2], S[2*a+1][0], S[2*a+1][1]);
            Pl[3] = resid_bf16(Ph[3], S[2*a+1][2], S[2*a+1][3]);

            int vrow = a * 16 + (sub & 1) * 8 + rin;
            #pragma unroll
            for (int bp = 0; bp < 4; bp++) {
                int ch = 2 * bp + (sub >> 1);
                uint32_t off = vrow * 128 + ((ch ^ (vrow & 7)) << 4);
                uint32_t vh[4], vl[4];
                ldsm_x4_t(vh, stb + AT_VH + off);
                ldsm_x4_t(vl, stb + AT_VL + off);
                mma_bf16(O[2*bp],   Ph, vh);
                mma_bf16(O[2*bp],   Ph, vl);
                mma_bf16(O[2*bp],   Pl, vh);
                mma_bf16(O[2*bp+1], Ph, vh + 2);
                mma_bf16(O[2*bp+1], Ph, vl + 2);
                mma_bf16(O[2*bp+1], Pl, vh + 2);
            }
        }
        __syncthreads();
        if (jt + 2 < SEQ / 64) load_kv(s, jt + 2);
    }

    // ---- epilogue: write bf16 hi/lo of O / l ----
    float inv0 = 1.f / l0, inv1 = 1.f / l1;
    size_t t0 = tok0 + qt * 128 + warp * 16 + g;
    size_t t1 = t0 + 8;
    #pragma unroll
    for (int b = 0; b < 8; b++) {
        int col = head * HDIM + b * 8 + 2 * t;
        float o00 = O[b][0] * inv0, o01 = O[b][1] * inv0;
        float o10 = O[b][2] * inv1, o11 = O[b][3] * inv1;
        uint32_t hp0 = pack_bf16(o00, o01);
        uint32_t hp1 = pack_bf16(o10, o11);
        *(uint32_t*)&ohi[t0 * DIM + col] = hp0;
        *(uint32_t*)&ohi[t1 * DIM + col] = hp1;
        *(uint32_t*)&olo[t0 * DIM + col] = resid_bf16(hp0, o00, o01);
        *(uint32_t*)&olo[t1 * DIM + col] = resid_bf16(hp1, o10, o11);
    }
}

// ----------------------------------------------------------------------------
// Launch
// ----------------------------------------------------------------------------
extern "C" void kernel_launch(void* const* d_in, const int* in_sizes, int n_in,
                              void* d_out, int out_size)
{
    const float* x     = (const float*)d_in[0];
    const float* w_qkv = (const float*)d_in[1];
    const float* w_out = (const float*)d_in[2];
    const float* b_out = (const float*)d_in[3];
    float* out = (float*)d_out;

    void *p_xhi, *p_xlo, *p_w1hi, *p_w1lo, *p_w2hi, *p_w2lo,
         *p_qh, *p_ql, *p_ahi, *p_alo;
    cudaGetSymbolAddress(&p_xhi, g_xhi);
    cudaGetSymbolAddress(&p_xlo, g_xlo);
    cudaGetSymbolAddress(&p_w1hi, g_w1hi);
    cudaGetSymbolAddress(&p_w1lo, g_w1lo);
    cudaGetSymbolAddress(&p_w2hi, g_w2hi);
    cudaGetSymbolAddress(&p_w2lo, g_w2lo);
    cudaGetSymbolAddress(&p_qh, g_qkvhi);
    cudaGetSymbolAddress(&p_ql, g_qkvlo);
    cudaGetSymbolAddress(&p_ahi, g_ahi);
    cudaGetSymbolAddress(&p_alo, g_alo);

    cudaFuncSetAttribute(gemm_mma<0>, cudaFuncAttributeMaxDynamicSharedMemorySize, GEMM_SMEM);
    cudaFuncSetAttribute(gemm_mma<1>, cudaFuncAttributeMaxDynamicSharedMemorySize, GEMM_SMEM);
    cudaFuncSetAttribute(attn_mma,    cudaFuncAttributeMaxDynamicSharedMemorySize, AT_SMEM);

    // 0) split inputs / weights into bf16 hi+lo
    split_kernel<<<(TOKENS * DIM / 4 + 255) / 256, 256>>>(
        x, (__nv_bfloat16*)p_xhi, (__nv_bfloat16*)p_xlo, TOKENS * DIM / 4);
    splitT_kernel<<<dim3(QKVDIM / 32, DIM / 32), 256>>>(
        w_qkv, (__nv_bfloat16*)p_w1hi, (__nv_bfloat16*)p_w1lo, DIM, QKVDIM);
    splitT_kernel<<<dim3(DIM / 32, DIM / 32), 256>>>(
        w_out, (__nv_bfloat16*)p_w2hi, (__nv_bfloat16*)p_w2lo, DIM, DIM);

    // 1) qkv = x @ w_qkv -> bf16 hi/lo directly     [8192, 3072]
    gemm_mma<1><<<dim3(QKVDIM / 128, TOKENS / 128), 256, GEMM_SMEM>>>(
        (const __nv_bfloat16*)p_xhi, (const __nv_bfloat16*)p_xlo,
        (const __nv_bfloat16*)p_w1hi, (const __nv_bfloat16*)p_w1lo,
        nullptr, nullptr,
        (__nv_bfloat16*)p_qh, (__nv_bfloat16*)p_ql, QKVDIM);

    // 2) attention -> bf16 hi/lo directly            [8192, 1024]
    attn_mma<<<dim3(SEQ / 128, HEADS, BATCH), 256, AT_SMEM>>>(
        (const __nv_bfloat16*)p_qh, (const __nv_bfloat16*)p_ql,
        (__nv_bfloat16*)p_ahi, (__nv_bfloat16*)p_alo);

    // 3) out = attn @ w_out + b                      [8192, 1024]
    gemm_mma<0><<<dim3(DIM / 128, TOKENS / 128), 256, GEMM_SMEM>>>(
        (const __nv_bfloat16*)p_ahi, (const __nv_bfloat16*)p_alo,
        (const __nv_bfloat16*)p_w2hi, (const __nv_bfloat16*)p_w2lo,
        b_out, out, nullptr, nullptr, DIM);
}

// round 5
// speedup vs baseline: 3.4079x; 1.0224x over previous
#include <cuda_runtime.h>
#include <cuda_bf16.h>
#include <cstdint>

// Problem constants
#define BATCH  8
#define SEQ    1024
#define DIM    1024
#define HEADS  16
#define HDIM   64
#define TOKENS (BATCH * SEQ)          // 8192
#define QKVDIM (3 * DIM)              // 3072
#define SCALE  0.03125f               // 1024^-0.5

// ---------------------------------------------------------------------------
// Scratch (device globals: allocation-guard safe)
// ---------------------------------------------------------------------------
__device__ __nv_bfloat16 g_xhi[(size_t)TOKENS * DIM];
__device__ __nv_bfloat16 g_xlo[(size_t)TOKENS * DIM];
__device__ __nv_bfloat16 g_w1hi[(size_t)QKVDIM * DIM];      // w_qkv^T [3072][1024]
__device__ __nv_bfloat16 g_w1lo[(size_t)QKVDIM * DIM];
__device__ __nv_bfloat16 g_w2hi[(size_t)DIM * DIM];         // w_out^T [1024][1024]
__device__ __nv_bfloat16 g_w2lo[(size_t)DIM * DIM];
__device__ __nv_bfloat16 g_qkvhi[(size_t)TOKENS * QKVDIM];  // qkv hi [8192][3072]
__device__ __nv_bfloat16 g_qkvlo[(size_t)TOKENS * QKVDIM];
__device__ __nv_bfloat16 g_ahi[(size_t)TOKENS * DIM];
__device__ __nv_bfloat16 g_alo[(size_t)TOKENS * DIM];

// ---------------------------------------------------------------------------
// Helpers
// ---------------------------------------------------------------------------
__device__ __forceinline__ uint32_t smem_u32(const void* p) {
    uint32_t a;
    asm("{ .reg .u64 t; cvta.to.shared.u64 t, %1; cvt.u32.u64 %0, t; }" : "=r"(a) : "l"(p));
    return a;
}

__device__ __forceinline__ void cp_async16(uint32_t dst, const void* src) {
    asm volatile("cp.async.cg.shared.global [%0], [%1], 16;\n" :: "r"(dst), "l"(src));
}
#define CP_COMMIT() asm volatile("cp.async.commit_group;\n" ::: "memory")
#define CP_WAIT2()  asm volatile("cp.async.wait_group 2;\n" ::: "memory")
#define CP_WAIT1()  asm volatile("cp.async.wait_group 1;\n" ::: "memory")
#define CP_WAIT0()  asm volatile("cp.async.wait_group 0;\n" ::: "memory")

__device__ __forceinline__ void ldsm_x4(uint32_t* r, uint32_t addr) {
    asm volatile("ldmatrix.sync.aligned.m8n8.x4.shared.b16 {%0,%1,%2,%3}, [%4];"
                 : "=r"(r[0]), "=r"(r[1]), "=r"(r[2]), "=r"(r[3]) : "r"(addr));
}

__device__ __forceinline__ void ldsm_x4_t(uint32_t* r, uint32_t addr) {
    asm volatile("ldmatrix.sync.aligned.m8n8.x4.trans.shared.b16 {%0,%1,%2,%3}, [%4];"
                 : "=r"(r[0]), "=r"(r[1]), "=r"(r[2]), "=r"(r[3]) : "r"(addr));
}

__device__ __forceinline__ void mma_bf16(float* d, const uint32_t* a, const uint32_t* b) {
    asm volatile("mma.sync.aligned.m16n8k16.row.col.f32.bf16.bf16.f32 "
                 "{%0,%1,%2,%3}, {%4,%5,%6,%7}, {%8,%9}, {%0,%1,%2,%3};"
                 : "+f"(d[0]), "+f"(d[1]), "+f"(d[2]), "+f"(d[3])
                 : "r"(a[0]), "r"(a[1]), "r"(a[2]), "r"(a[3]), "r"(b[0]), "r"(b[1]));
}

// pack two fp32 into bf16x2 (lo -> low half)
__device__ __forceinline__ uint32_t pack_bf16(float lo, float hi) {
    uint32_t d;
    asm("cvt.rn.bf16x2.f32 %0, %1, %2;" : "=r"(d) : "f"(hi), "f"(lo));
    return d;
}
// residual pair after bf16 truncation of (lo, hi) packed in hp
__device__ __forceinline__ uint32_t resid_bf16(uint32_t hp, float lo, float hi) {
    float h0 = __bfloat162float(__ushort_as_bfloat16((unsigned short)(hp & 0xffffu)));
    float h1 = __bfloat162float(__ushort_as_bfloat16((unsigned short)(hp >> 16)));
    return pack_bf16(lo - h0, hi - h1);
}

// ---------------------------------------------------------------------------
// Split-bf16 HMMA GEMM: C = (Ahi+Alo)[M,K] @ (Whi+Wlo)[N,K]^T
// OUT==0: write fp32 C (+bias).  OUT==1: write bf16 hi/lo pair (Chi, Clo).
// Block 128x128, BK=32, 256 threads, double-buffered cp.async, swizzled smem.
// 2 CTAs/SM for latency hiding (regs capped at 128, smem 2x64KB).
// ---------------------------------------------------------------------------
#define GK     1024
#define BK     32
#define NITER  (GK / BK)               // 32
#define TILEB  (128 * 64)              // [128 rows][32 bf16 = 64B]
#define STAGEB (4 * TILEB)             // 32 KB
#define GEMM_SMEM (2 * STAGEB)         // 64 KB

template<int OUT>
__global__ __launch_bounds__(256, 2) void gemm_mma(
    const __nv_bfloat16* __restrict__ Ahi, const __nv_bfloat16* __restrict__ Alo,
    const __nv_bfloat16* __restrict__ Whi, const __nv_bfloat16* __restrict__ Wlo,
    const float* __restrict__ bias, float* __restrict__ C,
    __nv_bfloat16* __restrict__ Chi, __nv_bfloat16* __restrict__ Clo, int N)
{
    extern __shared__ char sm[];
    const uint32_t sbase = smem_u32(sm);
    const int tid  = threadIdx.x;
    const int lane = tid & 31;
    const int warp = tid >> 5;
    const int wm = warp & 1;
    const int wn = warp >> 1;
    const int m0 = blockIdx.y * 128;
    const int n0 = blockIdx.x * 128;

    float acc[4][4][4];
    #pragma unroll
    for (int i = 0; i < 4; i++)
        #pragma unroll
        for (int j = 0; j < 4; j++)
            #pragma unroll
            for (int q = 0; q < 4; q++) acc[i][j][q] = 0.f;

    const __nv_bfloat16* gs[4] = {Ahi, Alo, Whi, Wlo};
    const int r0s[4] = {m0, m0, n0, n0};

    auto soff = [&](int s, int t) -> uint32_t { return sbase + s * STAGEB + t * TILEB; };

    auto load_stage = [&](int s, int k0) {
        #pragma unroll
        for (int t = 0; t < 4; t++) {
            const char* gp = (const char*)(gs[t] + (size_t)r0s[t] * GK + k0);
            #pragma unroll
            for (int j = 0; j < 2; j++) {
                int id = tid + j * 256;
                int r = id >> 2, c = id & 3;
                uint32_t sw = r * 64 + ((c ^ ((r >> 1) & 3)) << 4);
                cp_async16(soff(s, t) + sw, gp + (size_t)r * (GK * 2) + c * 16);
            }
        }
        CP_COMMIT();
    };

    load_stage(0, 0);
    load_stage(1, BK);

    const int sub = lane >> 3, rin = lane & 7;
    const int a_row_off = (sub & 1) * 8 + rin;
    const int a_chunk   = sub >> 1;
    const int b_row_off = (sub >> 1) * 8 + rin;
    const int b_chunk   = sub & 1;

    for (int it = 0; it < NITER; it++) {
        const int s = it & 1;
        if (it == NITER - 1) { CP_WAIT0(); } else { CP_WAIT1(); }
        __syncthreads();

        const uint32_t aH = soff(s, 0), aL = soff(s, 1);
        const uint32_t wH = soff(s, 2), wL = soff(s, 3);

        #pragma unroll
        for (int ks = 0; ks < 2; ks++) {
            uint32_t Ah[4][4], Al[4][4], Bh[4][2], Bl[4][2];

            #pragma unroll
            for (int mi = 0; mi < 4; mi++) {
                int row = wm * 64 + mi * 16 + a_row_off;
                int c = ks * 2 + a_chunk;
                uint32_t off = row * 64 + ((c ^ ((row >> 1) & 3)) << 4);
                ldsm_x4(Ah[mi], aH + off);
                ldsm_x4(Al[mi], aL + off);
            }
            #pragma unroll
            for (int p = 0; p < 2; p++) {
                int row = wn * 32 + p * 16 + b_row_off;
                int c = ks * 2 + b_chunk;
                uint32_t off = row * 64 + ((c ^ ((row >> 1) & 3)) << 4);
                uint32_t t0[4], t1[4];
                ldsm_x4(t0, wH + off);
                ldsm_x4(t1, wL + off);
                Bh[p*2  ][0] = t0[0]; Bh[p*2  ][1] = t0[1];
                Bh[p*2+1][0] = t0[2]; Bh[p*2+1][1] = t0[3];
                Bl[p*2  ][0] = t1[0]; Bl[p*2  ][1] = t1[1];
                Bl[p*2+1][0] = t1[2]; Bl[p*2+1][1] = t1[3];
            }

            #pragma unroll
            for (int mi = 0; mi < 4; mi++)
                #pragma unroll
                for (int ni = 0; ni < 4; ni++) {
                    mma_bf16(acc[mi][ni], Ah[mi], Bh[ni]);
                    mma_bf16(acc[mi][ni], Ah[mi], Bl[ni]);
                    mma_bf16(acc[mi][ni], Al[mi], Bh[ni]);
                }
        }
        __syncthreads();
        if (it + 2 < NITER) load_stage(s, (it + 2) * BK);
    }

    const int g = lane >> 2, c2 = (lane & 3) * 2;
    #pragma unroll
    for (int mi = 0; mi < 4; mi++) {
        int row = m0 + wm * 64 + mi * 16 + g;
        #pragma unroll
        for (int ni = 0; ni < 4; ni++) {
            int col = n0 + wn * 32 + ni * 8 + c2;
            if (OUT == 0) {
                float b0 = 0.f, b1 = 0.f;
                if (bias) { b0 = bias[col]; b1 = bias[col + 1]; }
                float2 v0 = make_float2(acc[mi][ni][0] + b0, acc[mi][ni][1] + b1);
                float2 v1 = make_float2(acc[mi][ni][2] + b0, acc[mi][ni][3] + b1);
                *(float2*)&C[(size_t)row * N + col] = v0;
                *(float2*)&C[(size_t)(row + 8) * N + col] = v1;
            } else {
                uint32_t hp0 = pack_bf16(acc[mi][ni][0], acc[mi][ni][1]);
                uint32_t hp1 = pack_bf16(acc[mi][ni][2], acc[mi][ni][3]);
                uint32_t lp0 = resid_bf16(hp0, acc[mi][ni][0], acc[mi][ni][1]);
                uint32_t lp1 = resid_bf16(hp1, acc[mi][ni][2], acc[mi][ni][3]);
                *(uint32_t*)&Chi[(size_t)row * N + col] = hp0;
                *(uint32_t*)&Chi[(size_t)(row + 8) * N + col] = hp1;
                *(uint32_t*)&Clo[(size_t)row * N + col] = lp0;
                *(uint32_t*)&Clo[(size_t)(row + 8) * N + col] = lp1;
            }
        }
    }
}

// ---------------------------------------------------------------------------
// fp32 -> bf16 hi/lo split (elementwise, float4)
// ---------------------------------------------------------------------------
__global__ __launch_bounds__(256) void split_kernel(
    const float* __restrict__ in, __nv_bfloat16* __restrict__ hi,
    __nv_bfloat16* __restrict__ lo, int n4)
{
    int i = blockIdx.x * blockDim.x + threadIdx.x;
    if (i >= n4) return;
    float4 v = ((const float4*)in)[i];
    __nv_bfloat16 h[4], l[4];
    float f[4] = {v.x, v.y, v.z, v.w};
    #pragma unroll
    for (int j = 0; j < 4; j++) {
        h[j] = __float2bfloat16(f[j]);
        l[j] = __float2bfloat16(f[j] - __bfloat162float(h[j]));
    }
    ((ushort4*)hi)[i] = make_ushort4(__bfloat16_as_ushort(h[0]), __bfloat16_as_ushort(h[1]),
                                     __bfloat16_as_ushort(h[2]), __bfloat16_as_ushort(h[3]));
    ((ushort4*)lo)[i] = make_ushort4(__bfloat16_as_ushort(l[0]), __bfloat16_as_ushort(l[1]),
                                     __bfloat16_as_ushort(l[2]), __bfloat16_as_ushort(l[3]));
}

// ---------------------------------------------------------------------------
// fp32 [K][N] -> transposed bf16 hi/lo [N][K]
// ---------------------------------------------------------------------------
__global__ __launch_bounds__(256) void splitT_kernel(
    const float* __restrict__ w, __nv_bfloat16* __restrict__ thi,
    __nv_bfloat16* __restrict__ tlo, int K, int N)
{
    __shared__ float t[32][33];
    const int n0 = blockIdx.x * 32, k0 = blockIdx.y * 32;
    const int tx = threadIdx.x & 31, ty = threadIdx.x >> 5;
    #pragma unroll
    for (int j = ty; j < 32; j += 8)
        t[j][tx] = w[(size_t)(k0 + j) * N + n0 + tx];
    __syncthreads();
    #pragma unroll
    for (int j = ty; j < 32; j += 8) {
        float v = t[tx][j];
        __nv_bfloat16 h = __float2bfloat16(v);
        __nv_bfloat16 l = __float2bfloat16(v - __bfloat162float(h));
        thi[(size_t)(n0 + j) * K + k0 + tx] = h;
        tlo[(size_t)(n0 + j) * K + k0 + tx] = l;
    }
}

// ---------------------------------------------------------------------------
// HMMA flash attention, split-bf16 (unchanged from Round 4 — known-good).
// ---------------------------------------------------------------------------
#define AT_Q    0
#define AT_QL   16384
#define AT_ST   32768
#define AT_STB  32768
#define AT_KH   0
#define AT_KL   8192
#define AT_VH   16384
#define AT_VL   24576
#define AT_SMEM (AT_ST + 2 * AT_STB)   // 98304

__global__ __launch_bounds__(256, 1) void attn_mma(
    const __nv_bfloat16* __restrict__ qh, const __nv_bfloat16* __restrict__ ql,
    __nv_bfloat16* __restrict__ ohi, __nv_bfloat16* __restrict__ olo)
{
    extern __shared__ char sm[];
    const uint32_t sb = smem_u32(sm);
    const int tid  = threadIdx.x;
    const int lane = tid & 31;
    const int warp = tid >> 5;
    const int sub = lane >> 3, rin = lane & 7;
    const int g = lane >> 2, t = lane & 3;

    const int qt = blockIdx.x, head = blockIdx.y, batch = blockIdx.z;
    const size_t tok0 = (size_t)batch * SEQ;
    const size_t qbase = (tok0 + qt * 128) * QKVDIM + head * HDIM;

    #pragma unroll
    for (int j = 0; j < 4; j++) {
        int id = tid + j * 256;
        int r = id >> 3, c = id & 7;
        uint32_t sw = r * 128 + ((c ^ (r & 7)) << 4);
        size_t go = (size_t)r * QKVDIM * 2 + c * 16;
        cp_async16(sb + AT_Q  + sw, (const char*)(qh + qbase) + go);
        cp_async16(sb + AT_QL + sw, (const char*)(ql + qbase) + go);
    }
    CP_COMMIT();

    auto load_kv = [&](int s, int jt) {
        size_t kb = (tok0 + jt * 64) * QKVDIM + DIM + head * HDIM;
        size_t vb = kb + DIM;
        uint32_t st = sb + AT_ST + s * AT_STB;
        #pragma unroll
        for (int j = 0; j < 2; j++) {
            int id = tid + j * 256;
            int r = id >> 3, c = id & 7;
            uint32_t sw = r * 128 + ((c ^ (r & 7)) << 4);
            size_t go = (size_t)r * QKVDIM * 2 + c * 16;
            cp_async16(st + AT_KH + sw, (const char*)(qh + kb) + go);
            cp_async16(st + AT_KL + sw, (const char*)(ql + kb) + go);
            cp_async16(st + AT_VH + sw, (const char*)(qh + vb) + go);
            cp_async16(st + AT_VL + sw, (const char*)(ql + vb) + go);
        }
        CP_COMMIT();
    };

    load_kv(0, 0);
    load_kv(1, 1);

    CP_WAIT2();
    __syncthreads();
    uint32_t Qh[4][4], Ql[4][4];
    {
        int row = warp * 16 + (sub & 1) * 8 + rin;
        #pragma unroll
        for (int s4 = 0; s4 < 4; s4++) {
            int ch = 2 * s4 + (sub >> 1);
            uint32_t off = row * 128 + ((ch ^ (row & 7)) << 4);
            ldsm_x4(Qh[s4], sb + AT_Q  + off);
            ldsm_x4(Ql[s4], sb + AT_QL + off);
        }
    }

    float m0 = -1e30f, m1 = -1e30f, l0 = 0.f, l1 = 0.f;
    float O[8][4];
    #pragma unroll
    for (int b = 0; b < 8; b++)
        #pragma unroll
        for (int q = 0; q < 4; q++) O[b][q] = 0.f;

    for (int jt = 0; jt < SEQ / 64; jt++) {
        const int s = jt & 1;
        if (jt == SEQ / 64 - 1) { CP_WAIT0(); } else { CP_WAIT1(); }
        __syncthreads();
        const uint32_t stb = sb + AT_ST + s * AT_STB;

        float S[8][4];
        #pragma unroll
        for (int b = 0; b < 8; b++)
            #pragma unroll
            for (int q = 0; q < 4; q++) S[b][q] = 0.f;

        #pragma unroll
        for (int s4 = 0; s4 < 4; s4++) {
            int bch = 2 * s4 + (sub & 1);
            #pragma unroll
            for (int jp = 0; jp < 4; jp++) {
                int row = jp * 16 + (sub >> 1) * 8 + rin;
                uint32_t off = row * 128 + ((bch ^ (row & 7)) << 4);
                uint32_t kh[4], kl[4];
                ldsm_x4(kh, stb + AT_KH + off);
                ldsm_x4(kl, stb + AT_KL + off);
                mma_bf16(S[2*jp],   Qh[s4], kh);
                mma_bf16(S[2*jp],   Qh[s4], kl);
                mma_bf16(S[2*jp],   Ql[s4], kh);
                mma_bf16(S[2*jp+1], Qh[s4], kh + 2);
                mma_bf16(S[2*jp+1], Qh[s4], kl + 2);
                mma_bf16(S[2*jp+1], Ql[s4], kh + 2);
            }
        }

        float mx0 = -1e30f, mx1 = -1e30f;
        #pragma unroll
        for (int b = 0; b < 8; b++) {
            #pragma unroll
            for (int q = 0; q < 4; q++) S[b][q] *= SCALE;
            mx0 = fmaxf(mx0, fmaxf(S[b][0], S[b][1]));
            mx1 = fmaxf(mx1, fmaxf(S[b][2], S[b][3]));
        }
        #pragma unroll
        for (int off = 1; off < 4; off <<= 1) {
            mx0 = fmaxf(mx0, __shfl_xor_sync(0xffffffffu, mx0, off));
            mx1 = fmaxf(mx1, __shfl_xor_sync(0xffffffffu, mx1, off));
        }
        float mn0 = fmaxf(m0, mx0), mn1 = fmaxf(m1, mx1);
        float al0 = __expf(m0 - mn0), al1 = __expf(m1 - mn1);
        m0 = mn0; m1 = mn1;

        float rs0 = 0.f, rs1 = 0.f;
        #pragma unroll
        for (int b = 0; b < 8; b++) {
            S[b][0] = __expf(S[b][0] - mn0); rs0 += S[b][0];
            S[b][1] = __expf(S[b][1] - mn0); rs0 += S[b][1];
            S[b][2] = __expf(S[b][2] - mn1); rs1 += S[b][2];
            S[b][3] = __expf(S[b][3] - mn1); rs1 += S[b][3];
        }
        #pragma unroll
        for (int off = 1; off < 4; off <<= 1) {
            rs0 += __shfl_xor_sync(0xffffffffu, rs0, off);
            rs1 += __shfl_xor_sync(0xffffffffu, rs1, off);
        }
        l0 = l0 * al0 + rs0;
        l1 = l1 * al1 + rs1;
        #pragma unroll
        for (int b = 0; b < 8; b++) {
            O[b][0] *= al0; O[b][1] *= al0;
            O[b][2] *= al1; O[b][3] *= al1;
        }

        #pragma unroll
        for (int a = 0; a < 4; a++) {
            uint32_t Ph[4], Pl[4];
            Ph[0] = pack_bf16(S[2*a][0],   S[2*a][1]);
            Ph[1] = pack_bf16(S[2*a][2],   S[2*a][3]);
            Ph[2] = pack_bf16(S[2*a+1][0], S[2*a+1][1]);
            Ph[3] = pack_bf16(S[2*a+1][2], S[2*a+1][3]);
            Pl[0] = resid_bf16(Ph[0], S[2*a][0],   S[2*a][1]);
            Pl[1] = resid_bf16(Ph[1], S[2*a][2],   S[2*a][3]);
            Pl[2] = resid_bf16(Ph[2], S[2*a+1][0], S[2*a+1][1]);
            Pl[3] = resid_bf16(Ph[3], S[2*a+1][2], S[2*a+1][3]);

            int vrow = a * 16 + (sub & 1) * 8 + rin;
            #pragma unroll
            for (int bp = 0; bp < 4; bp++) {
                int ch = 2 * bp + (sub >> 1);
                uint32_t off = vrow * 128 + ((ch ^ (vrow & 7)) << 4);
                uint32_t vh[4], vl[4];
                ldsm_x4_t(vh, stb + AT_VH + off);
                ldsm_x4_t(vl, stb + AT_VL + off);
                mma_bf16(O[2*bp],   Ph, vh);
                mma_bf16(O[2*bp],   Ph, vl);
                mma_bf16(O[2*bp],   Pl, vh);
                mma_bf16(O[2*bp+1], Ph, vh + 2);
                mma_bf16(O[2*bp+1], Ph, vl + 2);
                mma_bf16(O[2*bp+1], Pl, vh + 2);
            }
        }
        __syncthreads();
        if (jt + 2 < SEQ / 64) load_kv(s, jt + 2);
    }

    float inv0 = 1.f / l0, inv1 = 1.f / l1;
    size_t t0 = tok0 + qt * 128 + warp * 16 + g;
    size_t t1 = t0 + 8;
    #pragma unroll
    for (int b = 0; b < 8; b++) {
        int col = head * HDIM + b * 8 + 2 * t;
        float o00 = O[b][0] * inv0, o01 = O[b][1] * inv0;
        float o10 = O[b][2] * inv1, o11 = O[b][3] * inv1;
        uint32_t hp0 = pack_bf16(o00, o01);
        uint32_t hp1 = pack_bf16(o10, o11);
        *(uint32_t*)&ohi[t0 * DIM + col] = hp0;
        *(uint32_t*)&ohi[t1 * DIM + col] = hp1;
        *(uint32_t*)&olo[t0 * DIM + col] = resid_bf16(hp0, o00, o01);
        *(uint32_t*)&olo[t1 * DIM + col] = resid_bf16(hp1, o10, o11);
    }
}

// ----------------------------------------------------------------------------
// Launch
// ----------------------------------------------------------------------------
extern "C" void kernel_launch(void* const* d_in, const int* in_sizes, int n_in,
                              void* d_out, int out_size)
{
    const float* x     = (const float*)d_in[0];
    const float* w_qkv = (const float*)d_in[1];
    const float* w_out = (const float*)d_in[2];
    const float* b_out = (const float*)d_in[3];
    float* out = (float*)d_out;

    void *p_xhi, *p_xlo, *p_w1hi, *p_w1lo, *p_w2hi, *p_w2lo,
         *p_qh, *p_ql, *p_ahi, *p_alo;
    cudaGetSymbolAddress(&p_xhi, g_xhi);
    cudaGetSymbolAddress(&p_xlo, g_xlo);
    cudaGetSymbolAddress(&p_w1hi, g_w1hi);
    cudaGetSymbolAddress(&p_w1lo, g_w1lo);
    cudaGetSymbolAddress(&p_w2hi, g_w2hi);
    cudaGetSymbolAddress(&p_w2lo, g_w2lo);
    cudaGetSymbolAddress(&p_qh, g_qkvhi);
    cudaGetSymbolAddress(&p_ql, g_qkvlo);
    cudaGetSymbolAddress(&p_ahi, g_ahi);
    cudaGetSymbolAddress(&p_alo, g_alo);

    cudaFuncSetAttribute(gemm_mma<0>, cudaFuncAttributeMaxDynamicSharedMemorySize, GEMM_SMEM);
    cudaFuncSetAttribute(gemm_mma<1>, cudaFuncAttributeMaxDynamicSharedMemorySize, GEMM_SMEM);
    cudaFuncSetAttribute(attn_mma,    cudaFuncAttributeMaxDynamicSharedMemorySize, AT_SMEM);

    // 0) split inputs / weights into bf16 hi+lo
    split_kernel<<<(TOKENS * DIM / 4 + 255) / 256, 256>>>(
        x, (__nv_bfloat16*)p_xhi, (__nv_bfloat16*)p_xlo, TOKENS * DIM / 4);
    splitT_kernel<<<dim3(QKVDIM / 32, DIM / 32), 256>>>(
        w_qkv, (__nv_bfloat16*)p_w1hi, (__nv_bfloat16*)p_w1lo, DIM, QKVDIM);
    splitT_kernel<<<dim3(DIM / 32, DIM / 32), 256>>>(
        w_out, (__nv_bfloat16*)p_w2hi, (__nv_bfloat16*)p_w2lo, DIM, DIM);

    // 1) qkv = x @ w_qkv -> bf16 hi/lo directly     [8192, 3072]
    gemm_mma<1><<<dim3(QKVDIM / 128, TOKENS / 128), 256, GEMM_SMEM>>>(
        (const __nv_bfloat16*)p_xhi, (const __nv_bfloat16*)p_xlo,
        (const __nv_bfloat16*)p_w1hi, (const __nv_bfloat16*)p_w1lo,
        nullptr, nullptr,
        (__nv_bfloat16*)p_qh, (__nv_bfloat16*)p_ql, QKVDIM);

    // 2) attention -> bf16 hi/lo directly            [8192, 1024]
    attn_mma<<<dim3(SEQ / 128, HEADS, BATCH), 256, AT_SMEM>>>(
        (const __nv_bfloat16*)p_qh, (const __nv_bfloat16*)p_ql,
        (__nv_bfloat16*)p_ahi, (__nv_bfloat16*)p_alo);

    // 3) out = attn @ w_out + b                      [8192, 1024]
    gemm_mma<0><<<dim3(DIM / 128, TOKENS / 128), 256, GEMM_SMEM>>>(
        (const __nv_bfloat16*)p_ahi, (const __nv_bfloat16*)p_alo,
        (const __nv_bfloat16*)p_w2hi, (const __nv_bfloat16*)p_w2lo,
        b_out, out, nullptr, nullptr, DIM);
}